// round 3
// baseline (speedup 1.0000x reference)
#include <cuda_runtime.h>
#include <math.h>

// Fixed problem shapes
#define FCN   16
#define WT    593          // (FC+2)*FC + FC + FC*FC + FC + FC + 1
#define H_    152
#define W_    272
#define HW_   41344
#define B_    4
#define M_    32
#define BM_   128
#define EPS_  1.0e-4f

#define THREADS 128
#define PXPT    4                       // pixels per thread per iteration
#define PIXB    2048                    // pixels per block
#define NTILES  ((HW_ + PIXB - 1) / PIXB)   // 21

// Scratch accumulators (allocations forbidden) — zeroed each launch.
__device__ double g_neg_acc;
__device__ double g_pos_acc;

__global__ void zero_acc_kernel() {
    g_neg_acc = 0.0;
    g_pos_acc = 0.0;
}

// ---- packed f32x2 helpers (Blackwell FFMA2 path) ----
typedef unsigned long long u64;

__device__ __forceinline__ u64 pack2(float lo, float hi) {
    u64 r;
    asm("mov.b64 %0, {%1, %2};" : "=l"(r) : "f"(lo), "f"(hi));
    return r;
}
__device__ __forceinline__ void unpack2(u64 v, float& lo, float& hi) {
    asm("mov.b64 {%0, %1}, %2;" : "=f"(lo), "=f"(hi) : "l"(v));
}
__device__ __forceinline__ u64 fma2(u64 a, u64 b, u64 c) {
    u64 d;
    asm("fma.rn.f32x2 %0, %1, %2, %3;" : "=l"(d) : "l"(a), "l"(b), "l"(c));
    return d;
}
__device__ __forceinline__ u64 relu2(u64 a) {
    float lo, hi;
    unpack2(a, lo, hi);
    lo = fmaxf(lo, 0.0f);
    hi = fmaxf(hi, 0.0f);
    return pack2(lo, hi);
}

// Shared layout (duplicated: slot i holds [w_i, w_i] as a u64):
//   [0, 288)    w1t[c*16 + o] = w1[o][c]   (c in 0..17, o in 0..15)  -- TRANSPOSED
//   [288, 304)  b1[o]
//   [304, 560)  w2[o*16 + c]
//   [560, 576)  b2[o]
//   [576, 592)  w3[c]
//   [592]       b3
__global__ __launch_bounds__(THREADS)
void sch_loss_main(const float* __restrict__ sch_feat,
                   const float* __restrict__ conv_weight,
                   const float* __restrict__ mask,
                   const int*   __restrict__ pre_ind,
                   const float* __restrict__ target,
                   const int*   __restrict__ ind)
{
    __shared__ __align__(16) float sdup[2 * WT];
    __shared__ float sred[THREADS / 32];

    const int bm  = blockIdx.y;        // b*32 + m
    const int b   = bm >> 5;
    const int tid = threadIdx.x;
    const int pi  = pre_ind[bm];

    // Gather 593-float weight vector; w1 portion stored transposed.
    for (int s = tid; s < WT; s += THREADS) {
        int src;
        if (s < 288) {
            const int c = s >> 4;       // 0..17
            const int o = s & 15;       // 0..15
            src = o * 18 + c;           // original w1[o][c]
        } else {
            src = s;
        }
        const float v = conv_weight[((long long)b * WT + src) * HW_ + pi];
        sdup[2 * s]     = v;
        sdup[2 * s + 1] = v;
    }
    __syncthreads();

    const u64* __restrict__ swp = (const u64*)sdup;

    const float* __restrict__ sf = sch_feat + (long long)b * FCN * HW_;
    const float* __restrict__ tg = target   + (long long)bm * HW_;
    const int   posind = ind[bm];
    const float mval   = mask[bm];

    const float x0 = (float)(pi % W_);
    const float y0 = (float)pi / (float)W_;     // float division, matching reference
    const float inv128 = 1.0f / 128.0f;

    const int base  = blockIdx.x * PIXB;
    const int limit = (base + PIXB < HW_) ? (base + PIXB) : HW_;  // multiple of 4

    float negAcc = 0.0f;

    for (int p = base + PXPT * tid; p < limit; p += PXPT * THREADS) {
        // relative coords: 272 % 4 == 0 so no row wrap inside the 4-pixel group
        const int   px = p % W_;
        const float yr = ((float)(p / W_) - y0) * inv128;
        const float xr0 = ((float)(px    ) - x0) * inv128;
        const u64 xrA = pack2(xr0, xr0 + inv128);
        const u64 xrB = pack2(xr0 + 2.0f * inv128, xr0 + 3.0f * inv128);
        const u64 yrP = pack2(yr, yr);

        // ---- layer 1 (18 -> 16): feature-streaming, transposed weights ----
        u64 hA[FCN], hB[FCN];
        // init with bias (paired LDS.128)
        #pragma unroll
        for (int o = 0; o < FCN; o += 2) {
            const ulonglong2 bp = *(const ulonglong2*)&swp[288 + o];
            hA[o] = bp.x; hA[o + 1] = bp.y;
            hB[o] = bp.x; hB[o + 1] = bp.y;
        }
        // 16 feature channels
        #pragma unroll
        for (int c = 0; c < FCN; ++c) {
            const ulonglong2 fv = *(const ulonglong2*)(sf + (long long)c * HW_ + p);
            const u64 fAp = fv.x;
            const u64 fBp = fv.y;
            #pragma unroll
            for (int o = 0; o < FCN; o += 2) {
                const ulonglong2 w = *(const ulonglong2*)&swp[c * 16 + o];
                hA[o]     = fma2(w.x, fAp, hA[o]);
                hA[o + 1] = fma2(w.y, fAp, hA[o + 1]);
                hB[o]     = fma2(w.x, fBp, hB[o]);
                hB[o + 1] = fma2(w.y, fBp, hB[o + 1]);
            }
        }
        // x_rel channel (c = 16)
        #pragma unroll
        for (int o = 0; o < FCN; o += 2) {
            const ulonglong2 w = *(const ulonglong2*)&swp[16 * 16 + o];
            hA[o]     = fma2(w.x, xrA, hA[o]);
            hA[o + 1] = fma2(w.y, xrA, hA[o + 1]);
            hB[o]     = fma2(w.x, xrB, hB[o]);
            hB[o + 1] = fma2(w.y, xrB, hB[o + 1]);
        }
        // y_rel channel (c = 17)
        #pragma unroll
        for (int o = 0; o < FCN; o += 2) {
            const ulonglong2 w = *(const ulonglong2*)&swp[17 * 16 + o];
            hA[o]     = fma2(w.x, yrP, hA[o]);
            hA[o + 1] = fma2(w.y, yrP, hA[o + 1]);
            hB[o]     = fma2(w.x, yrP, hB[o]);
            hB[o + 1] = fma2(w.y, yrP, hB[o + 1]);
        }
        #pragma unroll
        for (int o = 0; o < FCN; ++o) {
            hA[o] = relu2(hA[o]);
            hB[o] = relu2(hB[o]);
        }

        // ---- layer 2 (16 -> 16) fused with layer 3 (16 -> 1) ----
        u64 zA = swp[592];
        u64 zB = zA;
        #pragma unroll
        for (int o = 0; o < FCN; ++o) {
            u64 aA = swp[560 + o];     // b2[o] (dup pair)
            u64 aB = aA;
            #pragma unroll
            for (int c = 0; c < FCN; c += 2) {
                const ulonglong2 w = *(const ulonglong2*)&swp[304 + o * 16 + c];
                aA = fma2(w.x, hA[c], aA);
                aA = fma2(w.y, hA[c + 1], aA);
                aB = fma2(w.x, hB[c], aB);
                aB = fma2(w.y, hB[c + 1], aB);
            }
            const u64 gA = relu2(aA);
            const u64 gB = relu2(aB);
            const u64 w3p = swp[576 + o];
            zA = fma2(w3p, gA, zA);
            zB = fma2(w3p, gB, zB);
        }

        // ---- epilogue: sigmoid + clip + focal terms ----
        float z[4];
        unpack2(zA, z[0], z[1]);
        unpack2(zB, z[2], z[3]);
        const float4 t4 = *(const float4*)(tg + p);
        const float tt[4] = {t4.x, t4.y, t4.z, t4.w};

        #pragma unroll
        for (int i = 0; i < 4; ++i) {
            float hm = 1.0f / (1.0f + __expf(-z[i]));
            hm = fminf(fmaxf(hm, EPS_), 1.0f - EPS_);
            float q = 1.0f - tt[i];
            q = q * q; q = q * q;                       // (1-t)^4
            negAcc += __logf(1.0f - hm) * hm * hm * q;
            if (p + i == posind) {
                const float om = 1.0f - hm;
                atomicAdd(&g_pos_acc, (double)(__logf(hm) * om * om * mval));
            }
        }
    }

    // ---- block reduction, one double atomic per block ----
    #pragma unroll
    for (int off = 16; off > 0; off >>= 1)
        negAcc += __shfl_down_sync(0xFFFFFFFFu, negAcc, off);
    if ((tid & 31) == 0) sred[tid >> 5] = negAcc;
    __syncthreads();
    if (tid < 32) {
        float v = (tid < THREADS / 32) ? sred[tid] : 0.0f;
        #pragma unroll
        for (int off = 2; off > 0; off >>= 1)
            v += __shfl_down_sync(0xFFFFFFFFu, v, off);
        if (tid == 0) atomicAdd(&g_neg_acc, (double)v);
    }
}

__global__ void finalize_kernel(const float* __restrict__ mask, float* __restrict__ out)
{
    if (threadIdx.x == 0) {
        float np = 0.0f;
        for (int i = 0; i < BM_; ++i) np += mask[i];
        const double neg = g_neg_acc;
        const double pos = g_pos_acc;
        double loss;
        if (np == 0.0f) loss = -neg;
        else            loss = -(pos + neg) / (double)fmaxf(np, 1.0f);
        out[0] = (float)loss;
    }
}

extern "C" void kernel_launch(void* const* d_in, const int* in_sizes, int n_in,
                              void* d_out, int out_size)
{
    const float* sch_feat    = (const float*)d_in[0];
    const float* conv_weight = (const float*)d_in[1];
    const float* mask        = (const float*)d_in[2];
    const int*   pre_ind     = (const int*)  d_in[3];
    const float* target      = (const float*)d_in[4];
    const int*   ind         = (const int*)  d_in[5];
    float* out = (float*)d_out;

    zero_acc_kernel<<<1, 1>>>();

    dim3 grid(NTILES, BM_);
    sch_loss_main<<<grid, THREADS>>>(sch_feat, conv_weight, mask, pre_ind, target, ind);

    finalize_kernel<<<1, 32>>>(mask, out);
}

// round 4
// speedup vs baseline: 1.0711x; 1.0711x over previous
#include <cuda_runtime.h>
#include <math.h>

// Fixed problem shapes
#define FCN   16
#define WT    593          // (FC+2)*FC + FC + FC*FC + FC + FC + 1
#define H_    152
#define W_    272
#define HW_   41344
#define B_    4
#define M_    32
#define BM_   128
#define EPS_  1.0e-4f

#define THREADS 128
#define PXPT    4                       // pixels per thread per iteration
#define PIXB    2048                    // pixels per block
#define NTILES  ((HW_ + PIXB - 1) / PIXB)   // 21

// Scratch accumulators (allocations forbidden) — zeroed each launch.
__device__ double g_neg_acc;
__device__ double g_pos_acc;

__global__ void zero_acc_kernel() {
    g_neg_acc = 0.0;
    g_pos_acc = 0.0;
}

// ---- packed f32x2 helpers (Blackwell FFMA2 path) ----
typedef unsigned long long u64;

__device__ __forceinline__ u64 pack2(float lo, float hi) {
    u64 r;
    asm("mov.b64 %0, {%1, %2};" : "=l"(r) : "f"(lo), "f"(hi));
    return r;
}
__device__ __forceinline__ void unpack2(u64 v, float& lo, float& hi) {
    asm("mov.b64 {%0, %1}, %2;" : "=f"(lo), "=f"(hi) : "l"(v));
}
__device__ __forceinline__ u64 fma2(u64 a, u64 b, u64 c) {
    u64 d;
    asm("fma.rn.f32x2 %0, %1, %2, %3;" : "=l"(d) : "l"(a), "l"(b), "l"(c));
    return d;
}
__device__ __forceinline__ u64 relu2(u64 a) {
    float lo, hi;
    unpack2(a, lo, hi);
    lo = fmaxf(lo, 0.0f);
    hi = fmaxf(hi, 0.0f);
    return pack2(lo, hi);
}

// Shared layout (duplicated: slot i holds [w_i, w_i] as one u64):
//   [0, 288)    w1[o*18 + c]   (rows of 18; row base even -> even-c pairs 16B-aligned)
//   [288, 304)  b1[o]
//   [304, 560)  w2[o*16 + c]
//   [560, 576)  b2[o]
//   [576, 592)  w3[c]
//   [592]       b3
__global__ __launch_bounds__(THREADS, 3)
void sch_loss_main(const float* __restrict__ sch_feat,
                   const float* __restrict__ conv_weight,
                   const float* __restrict__ mask,
                   const int*   __restrict__ pre_ind,
                   const float* __restrict__ target,
                   const int*   __restrict__ ind)
{
    __shared__ __align__(16) float sdup[2 * WT];
    __shared__ float sred[THREADS / 32];

    const int bm  = blockIdx.y;        // b*32 + m
    const int b   = bm >> 5;
    const int tid = threadIdx.x;
    const int pi  = pre_ind[bm];

    // Gather 593-float weight vector (strided over conv_weight (B, WT, H*W)), duplicated.
    for (int c = tid; c < WT; c += THREADS) {
        const float v = conv_weight[((long long)b * WT + c) * HW_ + pi];
        sdup[2 * c]     = v;
        sdup[2 * c + 1] = v;
    }
    __syncthreads();

    const u64* __restrict__ swp = (const u64*)sdup;

    const float* __restrict__ sf = sch_feat + (long long)b * FCN * HW_;
    const float* __restrict__ tg = target   + (long long)bm * HW_;
    const int   posind = ind[bm];
    const float mval   = mask[bm];

    const float x0 = (float)(pi % W_);
    const float y0 = (float)pi / (float)W_;     // float division, matching reference
    const float inv128 = 1.0f / 128.0f;

    const int base  = blockIdx.x * PIXB;
    const int limit = (base + PIXB < HW_) ? (base + PIXB) : HW_;  // multiple of 4

    float negAcc = 0.0f;

    for (int p = base + PXPT * tid; p < limit; p += PXPT * THREADS) {
        // relative coords: 272 % 4 == 0 so no row wrap inside the 4-pixel group
        const int   px = p % W_;
        const float yr = ((float)(p / W_) - y0) * inv128;
        const float xr0 = ((float)(px    ) - x0) * inv128;
        const u64 xrA = pack2(xr0, xr0 + inv128);
        const u64 xrB = pack2(xr0 + 2.0f * inv128, xr0 + 3.0f * inv128);
        const u64 yrP = pack2(yr, yr);

        // ---- layer 1 (18 -> 16): two batched half-loads of features, per-o rows ----
        u64 hA[FCN], hB[FCN];

        // init accumulators with bias (paired LDS.128 at even o)
        #pragma unroll
        for (int o = 0; o < FCN; o += 2) {
            const ulonglong2 bp = *(const ulonglong2*)&swp[288 + o];
            hA[o] = bp.x; hA[o + 1] = bp.y;
            hB[o] = bp.x; hB[o + 1] = bp.y;
        }

        // half-batches of 8 channels: batched LDG.128s, then accumulate
        #pragma unroll
        for (int half = 0; half < 2; ++half) {
            const int c0 = half * 8;
            u64 fA[8], fB[8];
            #pragma unroll
            for (int c = 0; c < 8; ++c) {
                const ulonglong2 v = *(const ulonglong2*)(sf + (long long)(c0 + c) * HW_ + p);
                fA[c] = v.x;
                fB[c] = v.y;
            }
            #pragma unroll
            for (int o = 0; o < FCN; ++o) {
                const int wb = o * 18 + c0;          // even base -> aligned pairs
                u64 aA = hA[o];
                u64 aB = hB[o];
                #pragma unroll
                for (int c = 0; c < 8; c += 2) {
                    const ulonglong2 w = *(const ulonglong2*)&swp[wb + c];
                    aA = fma2(w.x, fA[c], aA);
                    aA = fma2(w.y, fA[c + 1], aA);
                    aB = fma2(w.x, fB[c], aB);
                    aB = fma2(w.y, fB[c + 1], aB);
                }
                hA[o] = aA;
                hB[o] = aB;
            }
        }

        // coordinate channels (c = 16,17 -> aligned pair) + relu
        #pragma unroll
        for (int o = 0; o < FCN; ++o) {
            const ulonglong2 w = *(const ulonglong2*)&swp[o * 18 + 16];
            u64 aA = hA[o];
            u64 aB = hB[o];
            aA = fma2(w.x, xrA, aA); aA = fma2(w.y, yrP, aA);
            aB = fma2(w.x, xrB, aB); aB = fma2(w.y, yrP, aB);
            hA[o] = relu2(aA);
            hB[o] = relu2(aB);
        }

        // ---- layer 2 (16 -> 16) fused with layer 3 (16 -> 1) ----
        u64 zA = swp[592];
        u64 zB = zA;
        #pragma unroll
        for (int o = 0; o < FCN; ++o) {
            u64 aA = swp[560 + o];     // b2[o]
            u64 aB = aA;
            const int wb = 304 + o * 16;   // even base -> aligned pairs
            #pragma unroll
            for (int c = 0; c < FCN; c += 2) {
                const ulonglong2 w = *(const ulonglong2*)&swp[wb + c];
                aA = fma2(w.x, hA[c], aA);
                aA = fma2(w.y, hA[c + 1], aA);
                aB = fma2(w.x, hB[c], aB);
                aB = fma2(w.y, hB[c + 1], aB);
            }
            const u64 gA = relu2(aA);
            const u64 gB = relu2(aB);
            const u64 w3p = swp[576 + o];
            zA = fma2(w3p, gA, zA);
            zB = fma2(w3p, gB, zB);
        }

        // ---- epilogue: sigmoid + clip + focal terms ----
        float z[4];
        unpack2(zA, z[0], z[1]);
        unpack2(zB, z[2], z[3]);
        const float4 t4 = *(const float4*)(tg + p);
        const float tt[4] = {t4.x, t4.y, t4.z, t4.w};

        #pragma unroll
        for (int i = 0; i < 4; ++i) {
            float hm = 1.0f / (1.0f + __expf(-z[i]));
            hm = fminf(fmaxf(hm, EPS_), 1.0f - EPS_);
            float q = 1.0f - tt[i];
            q = q * q; q = q * q;                       // (1-t)^4
            negAcc += __logf(1.0f - hm) * hm * hm * q;
            if (p + i == posind) {
                const float om = 1.0f - hm;
                atomicAdd(&g_pos_acc, (double)(__logf(hm) * om * om * mval));
            }
        }
    }

    // ---- block reduction, one double atomic per block ----
    #pragma unroll
    for (int off = 16; off > 0; off >>= 1)
        negAcc += __shfl_down_sync(0xFFFFFFFFu, negAcc, off);
    if ((tid & 31) == 0) sred[tid >> 5] = negAcc;
    __syncthreads();
    if (tid < 32) {
        float v = (tid < THREADS / 32) ? sred[tid] : 0.0f;
        #pragma unroll
        for (int off = 2; off > 0; off >>= 1)
            v += __shfl_down_sync(0xFFFFFFFFu, v, off);
        if (tid == 0) atomicAdd(&g_neg_acc, (double)v);
    }
}

__global__ void finalize_kernel(const float* __restrict__ mask, float* __restrict__ out)
{
    if (threadIdx.x == 0) {
        float np = 0.0f;
        for (int i = 0; i < BM_; ++i) np += mask[i];
        const double neg = g_neg_acc;
        const double pos = g_pos_acc;
        double loss;
        if (np == 0.0f) loss = -neg;
        else            loss = -(pos + neg) / (double)fmaxf(np, 1.0f);
        out[0] = (float)loss;
    }
}

extern "C" void kernel_launch(void* const* d_in, const int* in_sizes, int n_in,
                              void* d_out, int out_size)
{
    const float* sch_feat    = (const float*)d_in[0];
    const float* conv_weight = (const float*)d_in[1];
    const float* mask        = (const float*)d_in[2];
    const int*   pre_ind     = (const int*)  d_in[3];
    const float* target      = (const float*)d_in[4];
    const int*   ind         = (const int*)  d_in[5];
    float* out = (float*)d_out;

    zero_acc_kernel<<<1, 1>>>();

    dim3 grid(NTILES, BM_);
    sch_loss_main<<<grid, THREADS>>>(sch_feat, conv_weight, mask, pre_ind, target, ind);

    finalize_kernel<<<1, 32>>>(mask, out);
}